// round 2
// baseline (speedup 1.0000x reference)
#include <cuda_runtime.h>
#include <cuda_bf16.h>

// Problem constants
#define B_   4
#define S_   16
#define H_   32
#define W_   32
#define CL_  64      // LSTM channels per layer (gates = 4*CL_ = 256)
#define TILE_H 8
#define NTHREADS 128
#define CHUNK 16

// Intermediate layer-0 hidden state: (B,S,64,H,W) fp32 = 16 MB static scratch.
__device__ float g_h0[(size_t)B_ * S_ * CL_ * H_ * W_];

typedef unsigned long long ull;

__device__ __forceinline__ float sigm(float x) {
    return 1.0f / (1.0f + __expf(-x));
}

// Pack a scalar into both lanes of an f32x2 register pair.
__device__ __forceinline__ ull pack2(float v) {
    ull r;
    asm("mov.b64 %0, {%1, %1};" : "=l"(r) : "f"(v));
    return r;
}

// Packed dual-FMA: d.lo = a.lo*b.lo + c.lo ; d.hi = a.hi*b.hi + c.hi
__device__ __forceinline__ ull fma2(ull a, ull b, ull c) {
    ull d;
    asm("fma.rn.f32x2 %0, %1, %2, %3;" : "=l"(d) : "l"(a), "l"(b), "l"(c));
    return d;
}

__device__ __forceinline__ void unpack2(ull v, float& lo, float& hi) {
    asm("mov.b64 {%0, %1}, %2;" : "=f"(lo), "=f"(hi) : "l"(v));
}

// Fused minLSTM layer.
// Block = 128 threads (tx=col 0..31, ty=0..3), tile = 8 rows x 32 cols, each
// thread owns 2 adjacent pixel rows (2*ty, 2*ty+1). 16 gate channels per block
// (4 LSTM channels: i,f,o,cand x4), packed pairwise into 8 f32x2 accumulators
// per pixel. Loops s=0..15 keeping cell state in registers.
template <int CIN>
__device__ __forceinline__ void layer_body(const float* __restrict__ x,
                                           const float* __restrict__ w,
                                           const float* __restrict__ bias,
                                           float* __restrict__ out)
{
    __shared__ __align__(16) float s_in[CHUNK * (TILE_H + 2) * (W_ + 2)]; // 16*10*34
    __shared__ __align__(16) float s_w[CHUNK * 9 * 16];                   // [ci][tap][j]
    __shared__ __align__(16) float s_b[16];

    const int tid  = threadIdx.x;
    const int ty   = tid >> 5;       // 0..3
    const int tx   = tid & 31;       // 0..31
    const int tile = blockIdx.x;     // 0..3
    const int grp  = blockIdx.y;     // 0..15
    const int b    = blockIdx.z;     // 0..3
    const int row0 = tile * TILE_H;
    const int py   = row0 + 2 * ty;  // first of the 2 pixel rows
    const int px   = tx;

    if (tid < 16) {
        int g = tid >> 2, cc = tid & 3;
        s_b[tid] = bias[g * CL_ + grp * 4 + cc];
    }
    __syncthreads();

    // cell states: 2 pixels x 4 LSTM channels
    float c_st[2][4];
#pragma unroll
    for (int p = 0; p < 2; ++p)
#pragma unroll
        for (int cc = 0; cc < 4; ++cc) c_st[p][cc] = 0.5f;

    for (int s = 0; s < S_; ++s) {
        // packed accumulators: pair p holds gate channels (2p, 2p+1)
        ull a0[8], a1[8];
        {
            const ulonglong2* bp = (const ulonglong2*)s_b;
            ulonglong2 bA = bp[0], bB = bp[1], bC = bp[2], bD = bp[3];
            a0[0] = bA.x; a0[1] = bA.y; a0[2] = bB.x; a0[3] = bB.y;
            a0[4] = bC.x; a0[5] = bC.y; a0[6] = bD.x; a0[7] = bD.y;
#pragma unroll
            for (int p = 0; p < 8; ++p) a1[p] = a0[p];
        }

        const float* xin = x + (size_t)(b * S_ + s) * CIN * (H_ * W_);

        for (int ch = 0; ch < CIN / CHUNK; ++ch) {
            // ---- stage input tile (16 ci x 10 rows x 34 cols, zero halo) ----
            for (int i = tid; i < CHUNK * (TILE_H + 2) * (W_ + 2); i += NTHREADS) {
                int ci  = i / ((TILE_H + 2) * (W_ + 2));
                int rem = i % ((TILE_H + 2) * (W_ + 2));
                int r   = rem / (W_ + 2);
                int cl  = rem % (W_ + 2);
                int gy  = row0 - 1 + r;
                int gx  = cl - 1;
                float v = 0.0f;
                if (gy >= 0 && gy < H_ && gx >= 0 && gx < W_)
                    v = xin[(ch * CHUNK + ci) * (H_ * W_) + gy * W_ + gx];
                s_in[i] = v;
            }
            // ---- stage weights: s_w[(ci*9 + tap)*16 + j], j = gate*4 + cc ----
            for (int i = tid; i < CHUNK * 9 * 16; i += NTHREADS) {
                int j   = i & 15;
                int t   = i >> 4;
                int tap = t % 9;
                int ci  = t / 9;
                int g   = j >> 2, cc = j & 3;
                int oc  = g * CL_ + grp * 4 + cc;
                s_w[i] = w[((size_t)oc * CIN + ch * CHUNK + ci) * 9 + tap];
            }
            __syncthreads();

            // ---- accumulate ----
            for (int ci = 0; ci < CHUNK; ++ci) {
                const float* xbase = &s_in[ci * (TILE_H + 2) * (W_ + 2)];
#pragma unroll
                for (int kx = 0; kx < 3; ++kx) {
                    const int cidx = tx + kx;
                    // 4 vertical x values serve both pixels' 3 ky taps
                    float v0 = xbase[(2 * ty + 0) * (W_ + 2) + cidx];
                    float v1 = xbase[(2 * ty + 1) * (W_ + 2) + cidx];
                    float v2 = xbase[(2 * ty + 2) * (W_ + 2) + cidx];
                    float v3 = xbase[(2 * ty + 3) * (W_ + 2) + cidx];
                    ull xv[4] = { pack2(v0), pack2(v1), pack2(v2), pack2(v3) };
#pragma unroll
                    for (int ky = 0; ky < 3; ++ky) {
                        const ulonglong2* wp =
                            (const ulonglong2*)&s_w[(ci * 9 + ky * 3 + kx) * 16];
                        ulonglong2 wA = wp[0], wB = wp[1], wC = wp[2], wD = wp[3];
                        ull x0 = xv[ky];      // pixel row 2ty   uses rows 2ty+ky
                        ull x1 = xv[ky + 1];  // pixel row 2ty+1 uses rows 2ty+1+ky
                        a0[0] = fma2(x0, wA.x, a0[0]); a0[1] = fma2(x0, wA.y, a0[1]);
                        a0[2] = fma2(x0, wB.x, a0[2]); a0[3] = fma2(x0, wB.y, a0[3]);
                        a0[4] = fma2(x0, wC.x, a0[4]); a0[5] = fma2(x0, wC.y, a0[5]);
                        a0[6] = fma2(x0, wD.x, a0[6]); a0[7] = fma2(x0, wD.y, a0[7]);
                        a1[0] = fma2(x1, wA.x, a1[0]); a1[1] = fma2(x1, wA.y, a1[1]);
                        a1[2] = fma2(x1, wB.x, a1[2]); a1[3] = fma2(x1, wB.y, a1[3]);
                        a1[4] = fma2(x1, wC.x, a1[4]); a1[5] = fma2(x1, wC.y, a1[5]);
                        a1[6] = fma2(x1, wD.x, a1[6]); a1[7] = fma2(x1, wD.y, a1[7]);
                    }
                }
            }
            __syncthreads();
        }

        // ---- gating + scan step + output, both pixels ----
#pragma unroll
        for (int p = 0; p < 2; ++p) {
            float A[16];
#pragma unroll
            for (int q = 0; q < 8; ++q) {
                ull v = p ? a1[q] : a0[q];
                unpack2(v, A[2 * q], A[2 * q + 1]);
            }
            float* outp = out + ((size_t)(b * S_ + s) * CL_ + grp * 4) * (H_ * W_)
                        + (py + p) * W_ + px;
#pragma unroll
            for (int cc = 0; cc < 4; ++cc) {
                float it = sigm(A[cc]);
                float ft = sigm(A[4 + cc]);
                float ot = sigm(A[8 + cc]);
                float cd = A[12 + cc];
                float gd = (cd >= 0.0f) ? (cd + 0.5f) : sigm(cd);
                float inv = 1.0f / (it + ft);
                float cn  = (ft * inv) * c_st[p][cc] + (it * inv) * gd;
                c_st[p][cc] = cn;
                outp[cc * (H_ * W_)] = ot * cn;
            }
        }
    }
}

__global__ void __launch_bounds__(128)
k_layer0(const float* __restrict__ x, const float* __restrict__ w,
         const float* __restrict__ b)
{
    layer_body<32>(x, w, b, g_h0);
}

__global__ void __launch_bounds__(128)
k_layer1(const float* __restrict__ w, const float* __restrict__ b,
         float* __restrict__ out)
{
    layer_body<64>(g_h0, w, b, out);
}

extern "C" void kernel_launch(void* const* d_in, const int* in_sizes, int n_in,
                              void* d_out, int out_size)
{
    const float* x  = (const float*)d_in[0];
    const float* w0 = (const float*)d_in[1];
    const float* b0 = (const float*)d_in[2];
    const float* w1 = (const float*)d_in[3];
    const float* b1 = (const float*)d_in[4];
    float* out = (float*)d_out;

    dim3 grid(4, 16, 4);   // spatial row-tiles x channel groups x batch
    k_layer0<<<grid, NTHREADS>>>(x, w0, b0);
    k_layer1<<<grid, NTHREADS>>>(w1, b1, out);
}